// round 7
// baseline (speedup 1.0000x reference)
#include <cuda_runtime.h>

#define NPT 4096
#define INV_EPS 10.0f
#define ITERS 50
#define RC 8                       // row chunks for column-partial reduction
#define ROWS_PER_RC (NPT / RC)     // 512

// Scratch (static device arrays: allocation-free per harness rules)
__device__ float g_K32[(size_t)NPT * NPT];     // K = exp(-C/eps), row-major fp32 (64 MB, L2-resident)
__device__ float g_colpart[RC * NPT];          // per-row-chunk column partial sums (128 KB)
__device__ float g_a[NPT];
__device__ float g_b[NPT];
__device__ float g_part[NPT];

// ---------------------------------------------------------------------------
// Prologue: K_ij = exp(-(|xi0-yj0|+|xi1-yj1|)/eps). One block per row.
// Also seeds colpart so the first reconstructed b == 1 (u = v = 0).
// ---------------------------------------------------------------------------
__global__ void k_init(const float* __restrict__ x, const float* __restrict__ y,
                       float nu) {
    const int i = blockIdx.x;
    const float xi0 = x[2 * i], xi1 = x[2 * i + 1];
    float* __restrict__ Krow = g_K32 + (size_t)i * NPT;
    for (int j = threadIdx.x; j < NPT; j += 256) {
        const float c = fabsf(xi0 - y[2 * j]) + fabsf(xi1 - y[2 * j + 1]);
        Krow[j] = __expf(-INV_EPS * c);
    }
    if (i == 0) {
        // b = nu / colsum; want b = 1 -> chunk0 = nu, rest 0
        for (int j = threadIdx.x; j < RC * NPT; j += 256)
            g_colpart[j] = (j < NPT) ? nu : 0.0f;
    }
}

// ---------------------------------------------------------------------------
// Row half-step: reconstruct b from colpart into smem, then a_i = mu/(K b)_i.
// 128 blocks x 1024 threads; warp per row, float4 streams from L2.
// ---------------------------------------------------------------------------
__global__ void __launch_bounds__(1024) k_row(float mu, float nu) {
    __shared__ __align__(16) float sb[NPT];
    const int t = threadIdx.x;

    // b_j = nu / sum_rc colpart[rc][j]   (fixed-order, deterministic)
    for (int j = t; j < NPT; j += 1024) {
        float s = 0.f;
#pragma unroll
        for (int rc = 0; rc < RC; rc++) s += g_colpart[rc * NPT + j];
        sb[j] = nu / s;
    }
    __syncthreads();

    const int row  = (blockIdx.x << 5) + (t >> 5);
    const int lane = t & 31;
    const float4* __restrict__ Krow = (const float4*)(g_K32 + (size_t)row * NPT);
    const float4* bv = (const float4*)sb;

    float4 acc = make_float4(0.f, 0.f, 0.f, 0.f);
#pragma unroll 8
    for (int j = lane; j < NPT / 4; j += 32) {
        const float4 k = Krow[j];
        const float4 b = bv[j];
        acc.x += k.x * b.x; acc.y += k.y * b.y;
        acc.z += k.z * b.z; acc.w += k.w * b.w;
    }
    float s = (acc.x + acc.y) + (acc.z + acc.w);
#pragma unroll
    for (int o = 16; o; o >>= 1) s += __shfl_xor_sync(0xFFFFFFFFu, s, o);
    if (lane == 0) g_a[row] = mu / s;
}

// ---------------------------------------------------------------------------
// Column half-step (partials): colpart[rc][j] = sum_{i in chunk rc} K_ij a_i.
// Reads K ROW-MAJOR (no transpose copy): block = 64-col x 512-row tile,
// 4 row-phases of 64 threads, coalesced 128B/warp loads, all L2 hits.
// grid (64 col-chunks, RC row-chunks) x 256 threads.
// ---------------------------------------------------------------------------
__global__ void __launch_bounds__(256) k_col() {
    __shared__ float sa[ROWS_PER_RC];
    __shared__ float part[4][64];
    const int t  = threadIdx.x;
    const int jc = blockIdx.x;
    const int rc = blockIdx.y;
    const int r0 = rc * ROWS_PER_RC;

    for (int r = t; r < ROWS_PER_RC; r += 256) sa[r] = g_a[r0 + r];
    __syncthreads();

    const int col = (jc << 6) + (t & 63);
    const int ph  = t >> 6;                       // 0..3 row phase
    const float* __restrict__ Kp = g_K32 + (size_t)r0 * NPT + col;

    float acc = 0.f;
#pragma unroll 8
    for (int r = ph; r < ROWS_PER_RC; r += 4)
        acc += Kp[(size_t)r * NPT] * sa[r];

    part[ph][t & 63] = acc;
    __syncthreads();
    if (t < 64)
        g_colpart[rc * NPT + (jc << 6) + t] =
            (part[0][t] + part[1][t]) + (part[2][t] + part[3][t]);
}

// Finalize b into global for the epilogue.
__global__ void k_bfin(float nu) {
    const int j = blockIdx.x * 1024 + threadIdx.x;
    float s = 0.f;
#pragma unroll
    for (int rc = 0; rc < RC; rc++) s += g_colpart[rc * NPT + j];
    g_b[j] = nu / s;
}

// ---------------------------------------------------------------------------
// Epilogue: pi_ij = a_i*K_ij*b_j; C recomputed from x,y; per-row cost partial.
// Block per row, 256 threads. Scalar stores (pi/C start at d_out+1).
// ---------------------------------------------------------------------------
__global__ void k_epilogue(const float* __restrict__ x, const float* __restrict__ y,
                           float* __restrict__ pi, float* __restrict__ Cout,
                           int do_write) {
    const int i = blockIdx.x;
    const int t = threadIdx.x;
    const float a   = g_a[i];
    const float xi0 = x[2 * i];
    const float xi1 = x[2 * i + 1];
    const float* __restrict__ Krow = g_K32 + (size_t)i * NPT;

    float s = 0.f;
    if (do_write) {
        for (int j = t; j < NPT; j += 256) {
            const float k = Krow[j];
            const float b = g_b[j];
            const float c = fabsf(xi0 - y[2 * j]) + fabsf(xi1 - y[2 * j + 1]);
            const float p = (a * k) * b;   // ordered to keep intermediates in range
            s += p * c;
            pi[(size_t)i * NPT + j]   = p;
            Cout[(size_t)i * NPT + j] = c;
        }
    } else {
        for (int j = t; j < NPT; j += 256) {
            const float k = Krow[j];
            const float b = g_b[j];
            const float c = fabsf(xi0 - y[2 * j]) + fabsf(xi1 - y[2 * j + 1]);
            s += ((a * k) * b) * c;
        }
    }
    __shared__ float sm[256];
    sm[t] = s;
    __syncthreads();
#pragma unroll
    for (int o = 128; o; o >>= 1) {
        if (t < o) sm[t] += sm[t + o];
        __syncthreads();
    }
    if (t == 0) g_part[i] = sm[0];
}

// Deterministic final reduction: cost = sum(pi * C); P=1 so cost^(1/P) = cost.
__global__ void k_final(float* __restrict__ out) {
    __shared__ float sm[1024];
    const int t = threadIdx.x;
    float s = g_part[t] + g_part[t + 1024] + g_part[t + 2048] + g_part[t + 3072];
    sm[t] = s;
    __syncthreads();
#pragma unroll
    for (int o = 512; o; o >>= 1) {
        if (t < o) sm[t] += sm[t + o];
        __syncthreads();
    }
    if (t == 0) out[0] = sm[0];
}

extern "C" void kernel_launch(void* const* d_in, const int* in_sizes, int n_in,
                              void* d_out, int out_size) {
    const float* x = (const float*)d_in[0];
    const float* y = (const float*)d_in[1];
    float* out = (float*)d_out;

    const float mu = 1.0f / (float)NPT + 1e-8f;  // exp(log_mu) == exp(log_nu)
    const float nu = mu;

    k_init<<<NPT, 256>>>(x, y, nu);

    for (int it = 0; it < ITERS; it++) {
        k_row<<<128, 1024>>>(mu, nu);        // b from colpart; a = mu/(K b)
        k_col<<<dim3(64, RC), 256>>>();      // colpart[rc][j] = sum K_ij a_i
    }
    k_bfin<<<4, 1024>>>(nu);                 // final b

    // Output layout (reference return order): [cost, pi (N*N), C (N*N)]
    const size_t nn = (size_t)NPT * NPT;
    const int do_write = (out_size >= (int)(1 + 2 * nn)) ? 1 : 0;
    float* pi = out + 1;
    float* C  = out + 1 + nn;

    k_epilogue<<<NPT, 256>>>(x, y, pi, C, do_write);
    k_final<<<1, 1024>>>(out);
}

// round 8
// speedup vs baseline: 1.3868x; 1.3868x over previous
#include <cuda_runtime.h>

#define NPT 4096
#define INV_EPS 10.0f
#define ITERS 50
#define FB 256                     // fused-iteration blocks (rows / 16)
#define RPB 16                     // rows per block

// Scratch (static device arrays: allocation-free per harness rules)
__device__ float g_K32[(size_t)NPT * NPT];             // K = exp(-C/eps), fp32 row-major (64 MB, L2-resident)
__device__ __align__(16) float g_colpart[FB * NPT];    // per-block column partials (4 MB)
__device__ __align__(16) float g_a[NPT];
__device__ __align__(16) float g_b[NPT];
__device__ float g_part[NPT];

// ---------------------------------------------------------------------------
// Prologue: K_ij = exp(-(|xi0-yj0|+|xi1-yj1|)/eps). Block per row.
// Seeds g_b = 1 (u = v = 0). MUFU(EX2)-bound, ~115us.
// ---------------------------------------------------------------------------
__global__ void k_init(const float* __restrict__ x, const float* __restrict__ y) {
    const int i = blockIdx.x;
    const float xi0 = x[2 * i], xi1 = x[2 * i + 1];
    float* __restrict__ Krow = g_K32 + (size_t)i * NPT;
    for (int j = threadIdx.x; j < NPT; j += 256) {
        const float c = fabsf(xi0 - y[2 * j]) + fabsf(xi1 - y[2 * j + 1]);
        Krow[j] = __expf(-INV_EPS * c);
    }
    if (i == 0)
        for (int j = threadIdx.x; j < NPT; j += 256) g_b[j] = 1.0f;
}

// ---------------------------------------------------------------------------
// Fused Sinkhorn iteration: reads K ONCE.
//   a_i = mu / (K b)_i   then   colpart[blk][j] += a_i * K_ij
// 256 blocks x 256 threads. Block owns 16 rows (4 batches of 4); warp w owns
// columns [512w, 512w+512). K-row segments held in registers between the dot
// phase and the accumulate phase, so the column pass costs zero extra LTS.
// ---------------------------------------------------------------------------
__global__ void __launch_bounds__(256, 2) k_iter(float mu) {
    const int w    = threadIdx.x >> 5;
    const int lane = threadIdx.x & 31;
    const int jq0  = w << 7;                     // float4 base index of warp's 512-col slice

    // b segment (512 floats of warp's slice) in registers
    const float4* __restrict__ bp = (const float4*)g_b;
    float4 bseg[4];
#pragma unroll
    for (int q = 0; q < 4; q++) bseg[q] = bp[jq0 + (q << 5) + lane];

    float4 acc[4] = {{0.f,0.f,0.f,0.f},{0.f,0.f,0.f,0.f},
                     {0.f,0.f,0.f,0.f},{0.f,0.f,0.f,0.f}};
    __shared__ float part[8][4];
    __shared__ float sa[4];
    const int r0 = blockIdx.x * RPB;

    for (int bt = 0; bt < 4; bt++) {
        const int rb = r0 + (bt << 2);
        float4 kr[4][4];
        float  p[4];
#pragma unroll
        for (int r = 0; r < 4; r++) {
            const float4* __restrict__ Kp =
                (const float4*)(g_K32 + (size_t)(rb + r) * NPT) + jq0;
            float s = 0.f;
#pragma unroll
            for (int q = 0; q < 4; q++) {
                const float4 k = Kp[(q << 5) + lane];
                kr[r][q] = k;
                s += k.x * bseg[q].x + k.y * bseg[q].y
                   + k.z * bseg[q].z + k.w * bseg[q].w;
            }
            p[r] = s;
        }
#pragma unroll
        for (int o = 16; o; o >>= 1) {
            p[0] += __shfl_xor_sync(0xFFFFFFFFu, p[0], o);
            p[1] += __shfl_xor_sync(0xFFFFFFFFu, p[1], o);
            p[2] += __shfl_xor_sync(0xFFFFFFFFu, p[2], o);
            p[3] += __shfl_xor_sync(0xFFFFFFFFu, p[3], o);
        }
        if (lane == 0) {
            part[w][0] = p[0]; part[w][1] = p[1];
            part[w][2] = p[2]; part[w][3] = p[3];
        }
        __syncthreads();
        if (threadIdx.x < 4) {
            const int r = threadIdx.x;
            float s = 0.f;
#pragma unroll
            for (int ww = 0; ww < 8; ww++) s += part[ww][r];   // fixed order
            const float a = mu / s;
            sa[r] = a;
            g_a[rb + r] = a;
        }
        __syncthreads();
#pragma unroll
        for (int r = 0; r < 4; r++) {
            const float a = sa[r];
#pragma unroll
            for (int q = 0; q < 4; q++) {
                acc[q].x = fmaf(a, kr[r][q].x, acc[q].x);
                acc[q].y = fmaf(a, kr[r][q].y, acc[q].y);
                acc[q].z = fmaf(a, kr[r][q].z, acc[q].z);
                acc[q].w = fmaf(a, kr[r][q].w, acc[q].w);
            }
        }
        __syncthreads();   // part/sa reused next batch
    }

    float4* __restrict__ cp = (float4*)(g_colpart + (size_t)blockIdx.x * NPT) + jq0;
#pragma unroll
    for (int q = 0; q < 4; q++) cp[(q << 5) + lane] = acc[q];
}

// ---------------------------------------------------------------------------
// b_j = nu / sum_{c=0..255} colpart[c][j]. Deterministic fixed-order reduce.
// grid 64 x 256: block owns 64 cols; thread quarter (t>>6) sums 64 chunks.
// ---------------------------------------------------------------------------
__global__ void __launch_bounds__(256) k_bred(float nu) {
    __shared__ float sp[4][64];
    const int t  = threadIdx.x;
    const int j  = (blockIdx.x << 6) + (t & 63);
    const int cq = t >> 6;
    float s = 0.f;
#pragma unroll 8
    for (int c = cq << 6; c < (cq << 6) + 64; c++)
        s += g_colpart[(size_t)c * NPT + j];
    sp[cq][t & 63] = s;
    __syncthreads();
    if (t < 64)
        g_b[(blockIdx.x << 6) + t] =
            nu / ((sp[0][t] + sp[1][t]) + (sp[2][t] + sp[3][t]));
}

// ---------------------------------------------------------------------------
// Epilogue: pi_ij = a_i*K_ij*b_j; C recomputed from x,y; per-row cost partial.
// ---------------------------------------------------------------------------
__global__ void k_epilogue(const float* __restrict__ x, const float* __restrict__ y,
                           float* __restrict__ pi, float* __restrict__ Cout,
                           int do_write) {
    const int i = blockIdx.x;
    const int t = threadIdx.x;
    const float a   = g_a[i];
    const float xi0 = x[2 * i];
    const float xi1 = x[2 * i + 1];
    const float* __restrict__ Krow = g_K32 + (size_t)i * NPT;

    float s = 0.f;
    if (do_write) {
        for (int j = t; j < NPT; j += 256) {
            const float k = Krow[j];
            const float b = g_b[j];
            const float c = fabsf(xi0 - y[2 * j]) + fabsf(xi1 - y[2 * j + 1]);
            const float p = (a * k) * b;
            s += p * c;
            pi[(size_t)i * NPT + j]   = p;
            Cout[(size_t)i * NPT + j] = c;
        }
    } else {
        for (int j = t; j < NPT; j += 256) {
            const float k = Krow[j];
            const float b = g_b[j];
            const float c = fabsf(xi0 - y[2 * j]) + fabsf(xi1 - y[2 * j + 1]);
            s += ((a * k) * b) * c;
        }
    }
    __shared__ float sm[256];
    sm[t] = s;
    __syncthreads();
#pragma unroll
    for (int o = 128; o; o >>= 1) {
        if (t < o) sm[t] += sm[t + o];
        __syncthreads();
    }
    if (t == 0) g_part[i] = sm[0];
}

// Deterministic final reduction: cost = sum(pi * C); P=1 so cost^(1/P) = cost.
__global__ void k_final(float* __restrict__ out) {
    __shared__ float sm[1024];
    const int t = threadIdx.x;
    float s = g_part[t] + g_part[t + 1024] + g_part[t + 2048] + g_part[t + 3072];
    sm[t] = s;
    __syncthreads();
#pragma unroll
    for (int o = 512; o; o >>= 1) {
        if (t < o) sm[t] += sm[t + o];
        __syncthreads();
    }
    if (t == 0) out[0] = sm[0];
}

extern "C" void kernel_launch(void* const* d_in, const int* in_sizes, int n_in,
                              void* d_out, int out_size) {
    const float* x = (const float*)d_in[0];
    const float* y = (const float*)d_in[1];
    float* out = (float*)d_out;

    const float mu = 1.0f / (float)NPT + 1e-8f;  // exp(log_mu) == exp(log_nu)
    const float nu = mu;

    k_init<<<NPT, 256>>>(x, y);

    for (int it = 0; it < ITERS; it++) {
        k_iter<<<FB, 256>>>(mu);     // a = mu/(K b); colpart = per-block K^T a
        k_bred<<<64, 256>>>(nu);     // b = nu / colsum
    }

    // Output layout (reference return order): [cost, pi (N*N), C (N*N)]
    const size_t nn = (size_t)NPT * NPT;
    const int do_write = (out_size >= (int)(1 + 2 * nn)) ? 1 : 0;
    float* pi = out + 1;
    float* C  = out + 1 + nn;

    k_epilogue<<<NPT, 256>>>(x, y, pi, C, do_write);
    k_final<<<1, 1024>>>(out);
}